// round 6
// baseline (speedup 1.0000x reference)
#include <cuda_runtime.h>

#define M 8192
#define NT 25            // Taylor terms n = 0..24
#define NBLK 740         // 148 SMs * 5 resident blocks (guaranteed co-resident)
#define NQUEUE 2048      // 1024 kv-groups + 1024 q-groups

// Scratch (allocation-free rule: __device__ globals; zero-initialized at load,
// and re-zeroed by the last finishing block each launch -> graph-replayable)
__device__ float g_q[M];
__device__ float g_C[NT], g_D[NT];
__device__ int   g_ctr     = 0;   // work-queue head
__device__ int   g_arrive  = 0;   // barrier arrivals
__device__ int   g_release = 0;   // barrier release flag
__device__ int   g_done    = 0;   // cleanup election

// ---------------------------------------------------------------------------
// Single fused persistent kernel.
// Phase 1: work-queue GEMV. Entry g<1024: rows 8g..8g+7 of BOTH Wk and Wv
//          (k,v staged in smem; warp 0 lanes 0-7 stream the 25 Taylor moment
//          terms straight into g_C/g_D with fire-and-forget atomics).
//          Entry g>=1024: rows of Wq -> g_q.
// Phase 2: grid barrier (all 740 blocks co-resident by construction).
// Phase 3: blocks 0-31 evaluate the two moment polynomials (Horner) per row.
// Phase 4: last block re-zeroes all device state for the next graph replay.
// ---------------------------------------------------------------------------
__global__ void __launch_bounds__(256, 5) fused_kernel(
    const float* __restrict__ x,
    const float* __restrict__ Wq, const float* __restrict__ bq,
    const float* __restrict__ Wk, const float* __restrict__ bk,
    const float* __restrict__ Wv, const float* __restrict__ bv,
    float* __restrict__ out)
{
    __shared__ float4 sx[M / 4];          // 32 KB: x staged once per block
    __shared__ float  sk[8], sv[8];       // k,v values for the current kv-group
    __shared__ float  sC[NT], sD[NT];     // moments for finalize
    __shared__ int    s_g;

    const int tid  = threadIdx.x;
    const int warp = tid >> 5;
    const int lane = tid & 31;

    const float4* x4 = reinterpret_cast<const float4*>(x);
#pragma unroll
    for (int i = 0; i < (M / 4) / 256; i++)
        sx[tid + i * 256] = x4[tid + i * 256];

    // ---------------- Phase 1: GEMV work queue ----------------
    for (;;) {
        if (tid == 0) s_g = atomicAdd(&g_ctr, 1);
        __syncthreads();                  // covers sx staging on iter 0
        const int g = s_g;
        __syncthreads();                  // all read s_g before next overwrite
        if (g >= NQUEUE) break;

        if (g < 1024) {
            // kv group: rows 8g..8g+7 of Wk AND Wv
            const int row = g * 8 + warp;
            const float4* Kr = reinterpret_cast<const float4*>(Wk + (size_t)row * M);
            const float4* Vr = reinterpret_cast<const float4*>(Wv + (size_t)row * M);

            float sumk = 0.f, sumv = 0.f;
#pragma unroll 8
            for (int c = lane; c < M / 4; c += 32) {
                float4 w  = Kr[c];
                float4 xx = sx[c];
                sumk += w.x * xx.x + w.y * xx.y + w.z * xx.z + w.w * xx.w;
            }
#pragma unroll 8
            for (int c = lane; c < M / 4; c += 32) {
                float4 w  = Vr[c];
                float4 xx = sx[c];
                sumv += w.x * xx.x + w.y * xx.y + w.z * xx.z + w.w * xx.w;
            }
#pragma unroll
            for (int o = 16; o; o >>= 1) {
                sumk += __shfl_xor_sync(0xffffffffu, sumk, o);
                sumv += __shfl_xor_sync(0xffffffffu, sumv, o);
            }
            if (lane == 0) {
                sk[warp] = sumk + bk[row];
                sv[warp] = sumv + bv[row];
            }
            __syncthreads();

            // Moments: warp 0, lanes 0-7, one j each. Array-free serial chain,
            // fire-and-forget atomics (hidden behind the streaming loads).
            if (warp == 0 && lane < 8) {
                const float k = sk[lane];
                const float v = sv[lane];
                float term = 1.f;                 // k^n / n!
#pragma unroll
                for (int n = 0; n < NT; n++) {
                    atomicAdd(&g_C[n], term);
                    atomicAdd(&g_D[n], term * v);
                    term *= k * (1.0f / (float)(n + 1));
                }
            }
            // sk/sv reuse is fenced by the two loop-top __syncthreads
        } else {
            // q group: rows of Wq -> g_q
            const int row = (g - 1024) * 8 + warp;
            const float4* Qr = reinterpret_cast<const float4*>(Wq + (size_t)row * M);

            float sum = 0.f;
#pragma unroll 8
            for (int c = lane; c < M / 4; c += 32) {
                float4 w  = Qr[c];
                float4 xx = sx[c];
                sum += w.x * xx.x + w.y * xx.y + w.z * xx.z + w.w * xx.w;
            }
#pragma unroll
            for (int o = 16; o; o >>= 1)
                sum += __shfl_xor_sync(0xffffffffu, sum, o);
            if (lane == 0)
                g_q[row] = sum + bq[row];
        }
    }

    // ---------------- Phase 2: grid barrier ----------------
    __threadfence();                       // publish g_q + atomics
    if (tid == 0) {
        const int t = atomicAdd(&g_arrive, 1);
        if (t == NBLK - 1) {
            __threadfence();
            atomicExch(&g_release, 1);
        } else {
            while (*(volatile int*)&g_release == 0) __nanosleep(128);
        }
    }
    __syncthreads();
    __threadfence();                       // acquire: make peers' writes visible

    // ---------------- Phase 3: finalize (blocks 0-31) ----------------
    if (blockIdx.x < 32) {
        if (tid < NT) { sC[tid] = g_C[tid]; sD[tid] = g_D[tid]; }
        __syncthreads();

        const int i = blockIdx.x * 256 + tid;
        const float a = g_q[i] * 0.03125f;   // 1/sqrt(1024) = 1/32

        float s0 = sC[NT - 1];
        float s1 = sD[NT - 1];
#pragma unroll
        for (int n = NT - 2; n >= 0; n--) {
            s0 = fmaf(s0, a, sC[n]);
            s1 = fmaf(s1, a, sD[n]);
        }
        out[i] = s1 / s0;
    }

    // ---------------- Phase 4: cleanup for next graph replay ----------------
    __threadfence();
    __syncthreads();
    if (tid == 0) {
        const int d = atomicAdd(&g_done, 1);
        if (d == NBLK - 1) {               // last block: everyone is past all reads
            g_ctr = 0; g_arrive = 0; g_release = 0; g_done = 0;
#pragma unroll
            for (int n = 0; n < NT; n++) { g_C[n] = 0.f; g_D[n] = 0.f; }
            __threadfence();
        }
    }
}

// ---------------------------------------------------------------------------
extern "C" void kernel_launch(void* const* d_in, const int* in_sizes, int n_in,
                              void* d_out, int out_size)
{
    const float* x  = (const float*)d_in[0];
    const float* Wq = (const float*)d_in[1];
    const float* bq = (const float*)d_in[2];
    const float* Wk = (const float*)d_in[3];
    const float* bk = (const float*)d_in[4];
    const float* Wv = (const float*)d_in[5];
    const float* bv = (const float*)d_in[6];

    fused_kernel<<<NBLK, 256>>>(x, Wq, bq, Wk, bk, Wv, bv, (float*)d_out);
}

// round 7
// speedup vs baseline: 2.2675x; 2.2675x over previous
#include <cuda_runtime.h>

#define M 8192
#define NT 25          // Taylor terms n = 0..24
#define FB 32          // finalize/moments blocks (co-resident: 32 <= 148 SMs)

// Scratch (allocation-free rule: __device__ globals)
__device__ float g_q[M], g_k[M], g_v[M];
__device__ float g_C[NT], g_D[NT];
__device__ int   g_arrive = 0;   // 32-block barrier (reset by last g_done incrementer)
__device__ int   g_done   = 0;

// ---------------------------------------------------------------------------
// K1: fused triple GEMV  y = W @ x + b  (classic grid, EXACT R2 structure —
// best measured: 123.3us @ 82.9% DRAM). Only change: __ldcs on the streaming
// weight loads (read-once data, evict-first).
// Block 0 zero-inits g_C/g_D for K2 (stream-ordered happens-before).
// ---------------------------------------------------------------------------
__global__ void __launch_bounds__(256) gemv3_kernel(
    const float* __restrict__ x,
    const float* __restrict__ Wq, const float* __restrict__ bq,
    const float* __restrict__ Wk, const float* __restrict__ bk,
    const float* __restrict__ Wv, const float* __restrict__ bv)
{
    __shared__ float4 sx[M / 4];          // 32 KB
    const int tid = threadIdx.x;

    if (blockIdx.x == 0 && tid < NT) { g_C[tid] = 0.f; g_D[tid] = 0.f; }

    const float4* x4 = reinterpret_cast<const float4*>(x);
#pragma unroll
    for (int i = 0; i < (M / 4) / 256; i++)
        sx[tid + i * 256] = x4[tid + i * 256];
    __syncthreads();

    const int mat  = blockIdx.x >> 10;    // 0:q 1:k 2:v
    const int blk  = blockIdx.x & 1023;
    const int warp = tid >> 5;
    const int lane = tid & 31;
    const int row  = blk * 8 + warp;

    const float* W;
    const float* b;
    float*       y;
    if (mat == 0)      { W = Wq; b = bq; y = g_q; }
    else if (mat == 1) { W = Wk; b = bk; y = g_k; }
    else               { W = Wv; b = bv; y = g_v; }

    const float4* Wr = reinterpret_cast<const float4*>(W + (size_t)row * M);

    float sum = 0.f;
#pragma unroll 8
    for (int c = lane; c < M / 4; c += 32) {
        float4 w  = __ldcs(&Wr[c]);       // streaming: read-once, evict-first
        float4 xx = sx[c];
        sum += w.x * xx.x + w.y * xx.y + w.z * xx.z + w.w * xx.w;
    }
#pragma unroll
    for (int o = 16; o; o >>= 1)
        sum += __shfl_xor_sync(0xffffffffu, sum, o);
    if (lane == 0)
        y[row] = sum + b[row];
}

// ---------------------------------------------------------------------------
// K2: moments + finalize merged (32 blocks x 256 threads = 8192 threads).
// Phase A: hierarchical moment reduction (registers -> shuffle -> shared
//          atomics -> 25 global REDs per block).  [R2-proven structure]
// Phase B: 32-block spin barrier on g_arrive.
// Phase C: Horner finalize, one row per thread.
// Reset:   last g_done incrementer zeroes both counters (all peers have
//          exited the spin by then) -> graph-replayable.
// ---------------------------------------------------------------------------
__global__ void __launch_bounds__(256) moments_finalize_kernel(float* __restrict__ out)
{
    __shared__ float sC[NT], sD[NT];
    const int tid = threadIdx.x;
    if (tid < NT) { sC[tid] = 0.f; sD[tid] = 0.f; }
    __syncthreads();

    const int j = blockIdx.x * 256 + tid;
    const float k = g_k[j];
    const float v = g_v[j];

    // ---- Phase A: per-thread moment terms, hierarchical reduce ----
    float C[NT], D[NT];
    float term = 1.f;                     // k^n / n!
#pragma unroll
    for (int n = 0; n < NT; n++) {
        C[n] = term;
        D[n] = term * v;
        term *= k * (1.0f / (float)(n + 1));
    }

#pragma unroll
    for (int n = 0; n < NT; n++) {
#pragma unroll
        for (int o = 16; o; o >>= 1) {
            C[n] += __shfl_xor_sync(0xffffffffu, C[n], o);
            D[n] += __shfl_xor_sync(0xffffffffu, D[n], o);
        }
    }
    if ((tid & 31) == 0) {
#pragma unroll
        for (int n = 0; n < NT; n++) {
            atomicAdd(&sC[n], C[n]);
            atomicAdd(&sD[n], D[n]);
        }
    }
    __syncthreads();
    if (tid < NT) {
        atomicAdd(&g_C[tid], sC[tid]);
        atomicAdd(&g_D[tid], sD[tid]);
    }

    // ---- Phase B: 32-block barrier ----
    __threadfence();
    __syncthreads();
    if (tid == 0) {
        atomicAdd(&g_arrive, 1);
        while (*(volatile int*)&g_arrive < FB) __nanosleep(64);
    }
    __syncthreads();
    __threadfence();                       // acquire peers' g_C/g_D REDs

    // ---- Phase C: Horner finalize (row i = j) ----
    if (tid < NT) { sC[tid] = g_C[tid]; sD[tid] = g_D[tid]; }
    __syncthreads();

    const float a = g_q[j] * 0.03125f;     // 1/sqrt(1024) = 1/32
    float s0 = sC[NT - 1];
    float s1 = sD[NT - 1];
#pragma unroll
    for (int n = NT - 2; n >= 0; n--) {
        s0 = fmaf(s0, a, sC[n]);
        s1 = fmaf(s1, a, sD[n]);
    }
    out[j] = s1 / s0;

    // ---- Reset for next graph replay ----
    __syncthreads();
    if (tid == 0) {
        const int d = atomicAdd(&g_done, 1);
        if (d == FB - 1) {                 // everyone has exited the spin
            g_arrive = 0;
            g_done   = 0;
            __threadfence();
        }
    }
}

// ---------------------------------------------------------------------------
extern "C" void kernel_launch(void* const* d_in, const int* in_sizes, int n_in,
                              void* d_out, int out_size)
{
    const float* x  = (const float*)d_in[0];
    const float* Wq = (const float*)d_in[1];
    const float* bq = (const float*)d_in[2];
    const float* Wk = (const float*)d_in[3];
    const float* bk = (const float*)d_in[4];
    const float* Wv = (const float*)d_in[5];
    const float* bv = (const float*)d_in[6];

    gemv3_kernel<<<3072, 256>>>(x, Wq, bq, Wk, bk, Wv, bv);
    moments_finalize_kernel<<<FB, 256>>>((float*)d_out);
}